// round 10
// baseline (speedup 1.0000x reference)
#include <cuda_runtime.h>
#include <cuda_bf16.h>

// PointPillarsScatter gather v9 (v8 + software-pipelined 4-iteration grid-stride):
//  - d_cellinfo[cell] = (n<<24) | sum(pid); n==1 (94.5% of occupied) needs no side list
//  - thread = 4 cells x 4 channels, ITERS=4 iterations (one batch per iteration),
//    NEXT iteration's cellinfo uint4 prefetched before processing the current one
//    -> the mandatory L2 hop is hidden behind the previous iteration's work.
//  - all output stores full-warp STG.128 __stcs.
//
// Inputs:
//   d_in[0]: pillar_feats  float32 [B=4, P=30000, C=64]
//   d_in[1]: pillar_coords int32   [B=4, P=30000, 2]  (y, x)
// Output: float32 [4, 64, 512, 512]

#define BEV_H 512
#define BEV_W 512
#define HW (BEV_H * BEV_W)      // 262144 = 2^18
#define C_DIM 64
#define P_DIM 30000
#define B_DIM 4
#define CAP 8
#define NGRP ((B_DIM * HW) / 4) // 262144 groups of 4 cells
#define ITERS B_DIM             // one batch per iteration
#define SLICE (HW / 4)          // 65536 groups per iteration

__device__ unsigned int   d_cellinfo[B_DIM * HW];     // 4 MB: (count<<24) | sum(pid)
__device__ unsigned short d_list[B_DIM * HW * CAP];   // 16 MB side lists (n>=2 only)

__global__ void pp_build_kernel(const int* __restrict__ coords) {
    int p = blockIdx.x * blockDim.x + threadIdx.x;
    if (p >= B_DIM * P_DIM) return;

    int2 yx = reinterpret_cast<const int2*>(coords)[p];
    int y = min(max(yx.x, 0), BEV_H - 1);
    int x = min(max(yx.y, 0), BEV_W - 1);

    int b   = p / P_DIM;
    int pid = p - b * P_DIM;
    int idx = b * HW + y * BEV_W + x;

    unsigned old = atomicAdd(&d_cellinfo[idx], (1u << 24) | (unsigned)pid);
    unsigned pos = old >> 24;
    if (pos < CAP) d_list[(size_t)idx * CAP + pos] = (unsigned short)pid;
}

__global__ __launch_bounds__(256) void pp_gather_kernel(const float* __restrict__ feats,
                                                        float* __restrict__ out) {
    int tid = blockIdx.x * blockDim.x + threadIdx.x;  // 0 .. 16*SLICE
    int gbase = tid & (SLICE - 1);  // group within batch (consecutive across warp)
    int chg   = tid >> 16;          // channel group 0..15 (4 channels each)
    int cell0 = gbase << 2;         // first cell within batch (constant over iters)

    const uint4* info = reinterpret_cast<const uint4*>(d_cellinfo);

    uint4 w = info[gbase];          // iteration 0 cellinfo (batch 0)

    #pragma unroll
    for (int i = 0; i < ITERS; i++) {
        // Prefetch next batch's cellinfo before touching this one's dependents.
        uint4 wn;
        if (i + 1 < ITERS) wn = info[gbase + (i + 1) * SLICE];

        unsigned wa[4] = {w.x, w.y, w.z, w.w};

        float acc[4][4];
        #pragma unroll
        for (int ci = 0; ci < 4; ci++)
            #pragma unroll
            for (int c = 0; c < 4; c++) acc[ci][c] = 0.0f;

        const float* fb = feats + (size_t)i * P_DIM * C_DIM + (chg << 2);
        int idx0 = i * HW + cell0;  // global cell index (for side lists)

        #pragma unroll
        for (int ci = 0; ci < 4; ci++) {
            unsigned n = wa[ci] >> 24;
            if (n == 0) continue;                 // ~89% of cells
            if (n == 1) {                         // pid embedded in the word
                unsigned pid = wa[ci] & 0xFFFFFFu;
                float4 v = *reinterpret_cast<const float4*>(fb + (size_t)pid * C_DIM);
                acc[ci][0] += v.x; acc[ci][1] += v.y; acc[ci][2] += v.z; acc[ci][3] += v.w;
            } else {                              // rare: side list
                int m = min((int)n, CAP);
                const unsigned short* lst = &d_list[(size_t)(idx0 + ci) * CAP];
                for (int j = 0; j < m; j++) {
                    unsigned pid = lst[j];
                    float4 v = *reinterpret_cast<const float4*>(fb + (size_t)pid * C_DIM);
                    acc[ci][0] += v.x; acc[ci][1] += v.y; acc[ci][2] += v.z; acc[ci][3] += v.w;
                }
            }
        }

        float* o = out + ((size_t)i * C_DIM + (size_t)(chg << 2)) * HW + cell0;
        #pragma unroll
        for (int c = 0; c < 4; c++) {
            float4 v = make_float4(acc[0][c], acc[1][c], acc[2][c], acc[3][c]);
            __stcs(reinterpret_cast<float4*>(o + (size_t)c * HW), v);
        }

        w = wn;
    }
}

extern "C" void kernel_launch(void* const* d_in, const int* in_sizes, int n_in,
                              void* d_out, int out_size) {
    const float* feats  = (const float*)d_in[0];
    const int*   coords = (const int*)d_in[1];
    float*       out    = (float*)d_out;

    // Zero the fused cell words (4 MB, graph-capturable)
    void* info_ptr = nullptr;
    cudaGetSymbolAddress(&info_ptr, d_cellinfo);
    cudaMemsetAsync(info_ptr, 0, (size_t)B_DIM * HW * sizeof(unsigned int));

    int n_pillars = B_DIM * P_DIM;                 // 120,000
    pp_build_kernel<<<(n_pillars + 255) / 256, 256>>>(coords);

    int n_threads = 16 * SLICE;                    // 1,048,576
    pp_gather_kernel<<<n_threads / 256, 256>>>(feats, out);
}

// round 11
// speedup vs baseline: 1.1023x; 1.1023x over previous
#include <cuda_runtime.h>
#include <cuda_bf16.h>

// PointPillarsScatter gather v10 (v8 skeleton, branchless hot kernel + fixup):
//  - d_cellinfo[cell] = (n<<24) | sum(pid). Hot gather handles ONLY n==0/n==1
//    (99.35% of cells) with a predicated feats load -> straight-line code, no loops.
//  - Cells with n>=2 are enqueued during build (exactly once, at pos==1) and a tiny
//    fixup kernel (1 warp/cell, ~7k cells) overwrites their 64 channels afterwards.
//  - thread = 4 cells x 4 channels (4.2M threads); stores full-warp STG.128 __stcs.
//
// Inputs:
//   d_in[0]: pillar_feats  float32 [B=4, P=30000, C=64]
//   d_in[1]: pillar_coords int32   [B=4, P=30000, 2]  (y, x)
// Output: float32 [4, 64, 512, 512]

#define BEV_H 512
#define BEV_W 512
#define HW (BEV_H * BEV_W)      // 262144 = 2^18
#define C_DIM 64
#define P_DIM 30000
#define B_DIM 4
#define CAP 8
#define NGRP ((B_DIM * HW) / 4) // 262144 groups of 4 cells
#define QCAP 16384              // expected ~6.8k n>=2 cells; 16k is >100 sigma safe

__device__ unsigned int   d_cellinfo[B_DIM * HW];     // 4 MB: (count<<24) | sum(pid)
__device__ unsigned short d_list[B_DIM * HW * CAP];   // 16 MB side lists
__device__ int            d_queue[QCAP];              // cells with n>=2
__device__ int            d_qcount;

__global__ void pp_build_kernel(const int* __restrict__ coords) {
    int p = blockIdx.x * blockDim.x + threadIdx.x;
    if (p >= B_DIM * P_DIM) return;

    int2 yx = reinterpret_cast<const int2*>(coords)[p];
    int y = min(max(yx.x, 0), BEV_H - 1);
    int x = min(max(yx.y, 0), BEV_W - 1);

    int b   = p / P_DIM;
    int pid = p - b * P_DIM;
    int idx = b * HW + y * BEV_W + x;

    unsigned old = atomicAdd(&d_cellinfo[idx], (1u << 24) | (unsigned)pid);
    unsigned pos = old >> 24;
    if (pos < CAP) d_list[(size_t)idx * CAP + pos] = (unsigned short)pid;
    if (pos == 1) {                       // second arrival: enqueue exactly once
        int q = atomicAdd(&d_qcount, 1);
        if (q < QCAP) d_queue[q] = idx;
    }
}

__global__ __launch_bounds__(256) void pp_gather_kernel(const float* __restrict__ feats,
                                                        float* __restrict__ out) {
    int tid = blockIdx.x * blockDim.x + threadIdx.x;  // 0 .. 16*NGRP
    int grp = tid & (NGRP - 1);     // cell group (consecutive across warp -> coalesced)
    int chg = tid >> 18;            // channel group 0..15 (4 channels each)

    int idx0  = grp << 2;
    int b     = idx0 >> 18;
    int cell0 = idx0 & (HW - 1);

    // One coalesced 16B load: count|pid for 4 cells (4MB, L2-resident)
    uint4 wv = *reinterpret_cast<const uint4*>(&d_cellinfo[idx0]);
    unsigned w[4] = {wv.x, wv.y, wv.z, wv.w};

    const float* fb = feats + (size_t)b * P_DIM * C_DIM + (chg << 2);

    // Straight-line: predicated load per cell (n==1 only; n>=2 fixed up later).
    float4 a[4];
    #pragma unroll
    for (int ci = 0; ci < 4; ci++) {
        float4 v = make_float4(0.f, 0.f, 0.f, 0.f);
        if ((w[ci] >> 24) == 1) {
            unsigned pid = w[ci] & 0xFFFFFFu;
            v = *reinterpret_cast<const float4*>(fb + (size_t)pid * C_DIM);
        }
        a[ci] = v;
    }

    float* o = out + ((size_t)b * C_DIM + (size_t)(chg << 2)) * HW + cell0;
    __stcs(reinterpret_cast<float4*>(o + 0 * (size_t)HW), make_float4(a[0].x, a[1].x, a[2].x, a[3].x));
    __stcs(reinterpret_cast<float4*>(o + 1 * (size_t)HW), make_float4(a[0].y, a[1].y, a[2].y, a[3].y));
    __stcs(reinterpret_cast<float4*>(o + 2 * (size_t)HW), make_float4(a[0].z, a[1].z, a[2].z, a[3].z));
    __stcs(reinterpret_cast<float4*>(o + 3 * (size_t)HW), make_float4(a[0].w, a[1].w, a[2].w, a[3].w));
}

// One warp per n>=2 cell: lane handles channels (lane, lane+32).
__global__ __launch_bounds__(256) void pp_fixup_kernel(const float* __restrict__ feats,
                                                       float* __restrict__ out) {
    int warp = (blockIdx.x * blockDim.x + threadIdx.x) >> 5;
    int lane = threadIdx.x & 31;
    int qn = min(d_qcount, QCAP);
    if (warp >= qn) return;

    int idx  = d_queue[warp];
    int b    = idx >> 18;
    int cell = idx & (HW - 1);

    int n = min((int)(d_cellinfo[idx] >> 24), CAP);
    const unsigned short* lst = &d_list[(size_t)idx * CAP];
    const float* fb = feats + (size_t)b * P_DIM * C_DIM;

    float s0 = 0.f, s1 = 0.f;
    for (int i = 0; i < n; i++) {
        const float* fp = fb + (size_t)lst[i] * C_DIM;
        s0 += fp[lane];
        s1 += fp[lane + 32];
    }
    out[((size_t)b * C_DIM + lane) * HW + cell]      = s0;
    out[((size_t)b * C_DIM + lane + 32) * HW + cell] = s1;
}

extern "C" void kernel_launch(void* const* d_in, const int* in_sizes, int n_in,
                              void* d_out, int out_size) {
    const float* feats  = (const float*)d_in[0];
    const int*   coords = (const int*)d_in[1];
    float*       out    = (float*)d_out;

    void* info_ptr = nullptr;
    cudaGetSymbolAddress(&info_ptr, d_cellinfo);
    cudaMemsetAsync(info_ptr, 0, (size_t)B_DIM * HW * sizeof(unsigned int));
    void* qc_ptr = nullptr;
    cudaGetSymbolAddress(&qc_ptr, d_qcount);
    cudaMemsetAsync(qc_ptr, 0, sizeof(int));

    int n_pillars = B_DIM * P_DIM;                 // 120,000
    pp_build_kernel<<<(n_pillars + 255) / 256, 256>>>(coords);

    int n_threads = 16 * NGRP;                     // 4,194,304
    pp_gather_kernel<<<n_threads / 256, 256>>>(feats, out);

    // Up to QCAP warps; inactive warps exit on the qcount guard.
    pp_fixup_kernel<<<QCAP * 32 / 256, 256>>>(feats, out);
}